// round 8
// baseline (speedup 1.0000x reference)
#include <cuda_runtime.h>
#include <math.h>

#define Bv 1024
#define Dv 8
#define Pv 128
#define Nv 1024
#define Hv 256
#define Wv 256
#define NTHR 512

#define GRAV   9.8f
#define DTv    0.01f
#define TQL    200.0f
#define SIGMAv 0.03f
#define KST    5000.0f
#define BMASS  40.0f
#define MAXC   6.4f
#define MAXPV  0.5f
#define SQRT3v 1.7320508075688772f

// ---- output segment offsets (floats), tuple order of reference ----
#define O_NX   ((size_t)0)
#define O_NXD  (O_NX  + (size_t)Bv*3)
#define O_NQ   (O_NXD + (size_t)Bv*3)
#define O_NOM  (O_NQ  + (size_t)Bv*4)
#define O_NTH  (O_NOM + (size_t)Bv*3)
#define O_XDD  (O_NTH + (size_t)Bv*Dv)
#define O_OMD  (O_XDD + (size_t)Bv*3)
#define O_THD  (O_OMD + (size_t)Bv*3)
#define O_FS   (O_THD + (size_t)Bv*Dv)
#define O_FF   (O_FS  + (size_t)Bv*Nv*3)
#define O_IC   (O_FF  + (size_t)Bv*Nv*3)
#define O_TQ   (O_IC  + (size_t)Bv*Nv)
#define O_RP   (O_TQ  + (size_t)Bv*3)
#define O_THR  (O_RP  + (size_t)Bv*Nv*3)

// fast tanh via MUFU EX2 path; exact limits at +-inf arguments
__device__ __forceinline__ float ftanh(float v) {
    float e = __expf(2.0f * v);
    return 1.0f - __fdividef(2.0f, e + 1.0f);
}

__global__ __launch_bounds__(NTHR, 2) void phys_kernel(
    const float* __restrict__ x,      const float* __restrict__ xd,
    const float* __restrict__ q,      const float* __restrict__ omega,
    const float* __restrict__ thetas, const float* __restrict__ controls,
    const float* __restrict__ z_grid, const float* __restrict__ z_grid_grad,
    const float* __restrict__ jp,     const float* __restrict__ jlp,
    const float* __restrict__ jlc,    const float* __restrict__ dpi,
    const float* __restrict__ dpm,    const float* __restrict__ bcog,
    const float* __restrict__ binert, const float* __restrict__ dd,
    float* __restrict__ out)
{
    const int b   = blockIdx.x;
    const int tid = threadIdx.x;

    __shared__ float sRw[9];
    __shared__ float sM[Dv][9];
    __shared__ float sT[Dv][3];
    __shared__ float sThr[Dv][3];
    __shared__ float sCL[Dv][3];
    __shared__ float sRI[Dv][9];
    __shared__ float sGdd[3];
    __shared__ float sGcog[3];
    __shared__ float sIn[9];
    __shared__ float sTM, sInvNC, sKD;
    __shared__ float sRed[16][6];

    const float xb0 = x[b*3+0], xb1 = x[b*3+1], xb2 = x[b*3+2];

    // ---- step A: R_world, gdd, total mass (tid 0) ----
    if (tid == 0) {
        float qw=q[b*4+0], qx=q[b*4+1], qy=q[b*4+2], qz=q[b*4+3];
        sRw[0]=1.f-2.f*(qy*qy+qz*qz); sRw[1]=2.f*(qx*qy-qw*qz); sRw[2]=2.f*(qx*qz+qw*qy);
        sRw[3]=2.f*(qx*qy+qw*qz); sRw[4]=1.f-2.f*(qx*qx+qz*qz); sRw[5]=2.f*(qy*qz-qw*qx);
        sRw[6]=2.f*(qx*qz-qw*qy); sRw[7]=2.f*(qy*qz+qw*qx); sRw[8]=1.f-2.f*(qx*qx+qy*qy);
        float tm = BMASS;
        #pragma unroll
        for (int d=0; d<Dv; d++) tm += dpm[d];
        sTM = tm;
        float d0=dd[0], d1=dd[1], d2=dd[2];
        sGdd[0]=sRw[0]*d0+sRw[1]*d1+sRw[2]*d2;
        sGdd[1]=sRw[3]*d0+sRw[4]*d1+sRw[5]*d2;
        sGdd[2]=sRw[6]*d0+sRw[7]*d1+sRw[8]*d2;
    }
    __syncthreads();

    // ---- step B: per-joint matrices (tids 0..7) ----
    if (tid < Dv) {
        const int d = tid;
        float th = thetas[b*Dv+d];
        float c = cosf(th), s = sinf(th);
        #pragma unroll
        for (int i=0;i<3;i++){
            sM[d][i*3+0] = c*sRw[i*3+0] - s*sRw[i*3+2];
            sM[d][i*3+1] = sRw[i*3+1];
            sM[d][i*3+2] = s*sRw[i*3+0] + c*sRw[i*3+2];
        }
        float jp0=jp[d*3+0], jp1=jp[d*3+1], jp2=jp[d*3+2];
        sT[d][0]=sRw[0]*jp0+sRw[1]*jp1+sRw[2]*jp2 + xb0;
        sT[d][1]=sRw[3]*jp0+sRw[4]*jp1+sRw[5]*jp2 + xb1;
        sT[d][2]=sRw[6]*jp0+sRw[7]*jp1+sRw[8]*jp2 + xb2;
        float l0=jlc[d*3+0], l1=jlc[d*3+1], l2=jlc[d*3+2];
        sCL[d][0] = c*l0 + s*l2 + jp0;
        sCL[d][1] = l1 + jp1;
        sCL[d][2] = -s*l0 + c*l2 + jp2;
        const float* Im = dpi + d*9;
        float t0[3], t1[3], t2[3];
        #pragma unroll
        for (int j=0;j<3;j++){
            t0[j] =  c*Im[0*3+j] + s*Im[2*3+j];
            t1[j] =  Im[1*3+j];
            t2[j] = -s*Im[0*3+j] + c*Im[2*3+j];
        }
        sRI[d][0]= c*t0[0]+s*t0[2]; sRI[d][1]=t0[1]; sRI[d][2]=-s*t0[0]+c*t0[2];
        sRI[d][3]= c*t1[0]+s*t1[2]; sRI[d][4]=t1[1]; sRI[d][5]=-s*t1[0]+c*t1[2];
        sRI[d][6]= c*t2[0]+s*t2[2]; sRI[d][7]=t2[1]; sRI[d][8]=-s*t2[0]+c*t2[2];
        float d0=dd[0], d1=dd[1], d2=dd[2];
        float u0 = c*d0 + s*d2, u1 = d1, u2 = -s*d0 + c*d2;
        float vc = controls[b*2*Dv + d];
        sThr[d][0]=(sRw[0]*u0+sRw[1]*u1+sRw[2]*u2)*vc;
        sThr[d][1]=(sRw[3]*u0+sRw[4]*u1+sRw[5]*u2)*vc;
        sThr[d][2]=(sRw[6]*u0+sRw[7]*u1+sRw[8]*u2)*vc;
    }
    __syncthreads();

    // ---- step C: cog + world inertia (tid 0) ----
    if (tid == 0) {
        float tm = sTM;
        float cg0 = BMASS*bcog[0], cg1 = BMASS*bcog[1], cg2 = BMASS*bcog[2];
        #pragma unroll
        for (int d=0; d<Dv; d++){
            float m = dpm[d];
            cg0 += m*sCL[d][0]; cg1 += m*sCL[d][1]; cg2 += m*sCL[d][2];
        }
        float itm = 1.0f/tm;
        cg0*=itm; cg1*=itm; cg2*=itm;
        float Io[9];
        #pragma unroll
        for (int i=0;i<9;i++) Io[i] = binert[i];
        {
            float e0=bcog[0]-cg0, e1=bcog[1]-cg1, e2=bcog[2]-cg2;
            float s2 = e0*e0+e1*e1+e2*e2;
            Io[0]+=BMASS*(s2-e0*e0); Io[1]+=BMASS*(-e0*e1);  Io[2]+=BMASS*(-e0*e2);
            Io[3]+=BMASS*(-e1*e0);  Io[4]+=BMASS*(s2-e1*e1); Io[5]+=BMASS*(-e1*e2);
            Io[6]+=BMASS*(-e2*e0);  Io[7]+=BMASS*(-e2*e1);   Io[8]+=BMASS*(s2-e2*e2);
        }
        #pragma unroll
        for (int d=0; d<Dv; d++){
            float m = dpm[d];
            float e0=sCL[d][0]-cg0, e1=sCL[d][1]-cg1, e2=sCL[d][2]-cg2;
            float s2 = e0*e0+e1*e1+e2*e2;
            Io[0]+=sRI[d][0]+m*(s2-e0*e0); Io[1]+=sRI[d][1]+m*(-e0*e1);  Io[2]+=sRI[d][2]+m*(-e0*e2);
            Io[3]+=sRI[d][3]+m*(-e1*e0);  Io[4]+=sRI[d][4]+m*(s2-e1*e1); Io[5]+=sRI[d][5]+m*(-e1*e2);
            Io[6]+=sRI[d][6]+m*(-e2*e0);  Io[7]+=sRI[d][7]+m*(-e2*e1);   Io[8]+=sRI[d][8]+m*(s2-e2*e2);
        }
        float tmp[9];
        #pragma unroll
        for (int i=0;i<3;i++)
            #pragma unroll
            for (int j=0;j<3;j++)
                tmp[i*3+j] = sRw[i*3+0]*Io[0*3+j] + sRw[i*3+1]*Io[1*3+j] + sRw[i*3+2]*Io[2*3+j];
        #pragma unroll
        for (int i=0;i<3;i++)
            #pragma unroll
            for (int j=0;j<3;j++)
                sIn[i*3+j] = tmp[i*3+0]*sRw[j*3+0] + tmp[i*3+1]*sRw[j*3+1] + tmp[i*3+2]*sRw[j*3+2];
        sGcog[0]=sRw[0]*cg0+sRw[1]*cg1+sRw[2]*cg2 + xb0;
        sGcog[1]=sRw[3]*cg0+sRw[4]*cg1+sRw[5]*cg2 + xb1;
        sGcog[2]=sRw[6]*cg0+sRw[7]*cg1+sRw[8]*cg2 + xb2;
    }
    __syncthreads();

    // ---- phase A: points, gathers, contact (state kept in registers) ----
    const float* zg  = z_grid      + (size_t)b*Hv*Wv;
    const float* gxg = z_grid_grad + (size_t)b*2*Hv*Wv;
    const float* gyg = gxg + (size_t)Hv*Wv;

    float rp[2][3], nrm[2][3], dhv[2], icv[2];
    float icsum = 0.f;
    #pragma unroll
    for (int k=0;k<2;k++){
        int n = tid + k*NTHR;
        int d = n >> 7;
        const float* lp = jlp + (size_t)n*3;
        float l0=__ldg(lp+0), l1=__ldg(lp+1), l2=__ldg(lp+2);
        float r0 = sM[d][0]*l0 + sM[d][1]*l1 + sM[d][2]*l2 + sT[d][0];
        float r1 = sM[d][3]*l0 + sM[d][4]*l1 + sM[d][5]*l2 + sT[d][1];
        float r2 = sM[d][6]*l0 + sM[d][7]*l1 + sM[d][8]*l2 + sT[d][2];
        rp[k][0]=r0; rp[k][1]=r1; rp[k][2]=r2;
        size_t o3 = O_RP + ((size_t)b*Nv + n)*3;
        out[o3+0]=r0; out[o3+1]=r1; out[o3+2]=r2;

        float u = (r0 + MAXC) / (2.0f*MAXC) * (float)(Wv-1);
        float v = (r1 + MAXC) / (2.0f*MAXC) * (float)(Hv-1);
        u = fminf(fmaxf(u, 0.0f), (float)(Wv-1) - 1e-5f);
        v = fminf(fmaxf(v, 0.0f), (float)(Hv-1) - 1e-5f);
        int u0 = (int)u, v0 = (int)v;
        float fu = u - (float)u0, fv = v - (float)v0;
        int idx = v0*Wv + u0;
        float w00=(1.f-fu)*(1.f-fv), w01=fu*(1.f-fv), w10=(1.f-fu)*fv, w11=fu*fv;
        float zs = __ldg(zg+idx)*w00 + __ldg(zg+idx+1)*w01 + __ldg(zg+idx+Wv)*w10 + __ldg(zg+idx+Wv+1)*w11;
        float gx = __ldg(gxg+idx)*w00 + __ldg(gxg+idx+1)*w01 + __ldg(gxg+idx+Wv)*w10 + __ldg(gxg+idx+Wv+1)*w11;
        float gy = __ldg(gyg+idx)*w00 + __ldg(gyg+idx+1)*w01 + __ldg(gyg+idx+Wv)*w10 + __ldg(gyg+idx+Wv+1)*w11;

        // n = normalized([-gx,-gy,1]); rsqrtf (eps dropped: arg >= 1)
        float inv = rsqrtf(gx*gx + gy*gy + 1.0f);
        float nx=-gx*inv, ny=-gy*inv, nz=inv;
        float dh = (r2 - zs)*nz;
        float ic = 0.5f*(1.0f + ftanh(-dh*(SQRT3v/SIGMAv)));
        nrm[k][0]=nx; nrm[k][1]=ny; nrm[k][2]=nz;
        dhv[k]=dh; icv[k]=ic; icsum += ic;
    }
    // reduce num_contacts
    #pragma unroll
    for (int o=16;o>0;o>>=1) icsum += __shfl_xor_sync(0xffffffffu, icsum, o);
    if ((tid & 31) == 0) sRed[tid>>5][0] = icsum;
    __syncthreads();
    if (tid == 0) {
        float s = 0.f;
        #pragma unroll
        for (int w=0;w<16;w++) s += sRed[w][0];
        float nc = fmaxf(s, 1.0f);
        sInvNC = 1.0f/nc;
        sKD = sqrtf(sTM*KST/nc);
    }
    __syncthreads();

    // ---- phase B: forces ----
    const float xd0=xd[b*3+0], xd1=xd[b*3+1], xd2=xd[b*3+2];
    const float om0=omega[b*3+0], om1=omega[b*3+1], om2=omega[b*3+2];
    const float invnc = sInvNC, kd = sKD;
    const float g0=sGdd[0], g1=sGdd[1], g2=sGdd[2];
    const float gc0=sGcog[0], gc1=sGcog[1], gc2=sGcog[2];
    float as0=0.f, as1=0.f, as2=0.f, ts0=0.f, ts1=0.f, ts2=0.f;
    #pragma unroll
    for (int k=0;k<2;k++){
        int n = tid + k*NTHR;
        int d = n >> 7;
        float cc0 = rp[k][0]-gc0, cc1 = rp[k][1]-gc1, cc2 = rp[k][2]-gc2;
        float xp0 = xd0 + om1*cc2 - om2*cc1;
        float xp1 = xd1 + om2*cc0 - om0*cc2;
        float xp2 = xd2 + om0*cc1 - om1*cc0;
        float nx=nrm[k][0], ny=nrm[k][1], nz=nrm[k][2];
        float ic=icv[k], dh=dhv[k];
        float xdn = xp0*nx + xp1*ny + xp2*nz;
        float sf = -(KST*dh*ic + kd*xdn)*ic*invnc;
        float fs0 = sf*nx, fs1 = sf*ny, fs2 = sf*nz;
        float Nm = fabsf(sf);                      // |F_spring| since n is unit
        float gn = g0*nx + g1*ny + g2*nz;
        float fw0 = g0-gn*nx, fw1 = g1-gn*ny, fw2 = g2-gn*nz;
        float fni = rsqrtf(fw0*fw0+fw1*fw1+fw2*fw2);
        fw0*=fni; fw1*=fni; fw2*=fni;
        // lat = cross(fwd, n): fwd ⊥ n, both unit → already unit; skip renorm
        float lt0 = fw1*nz - fw2*ny, lt1 = fw2*nx - fw0*nz, lt2 = fw0*ny - fw1*nx;
        float th0=sThr[d][0], th1=sThr[d][1], th2=sThr[d][2];
        float dv0=th0-xp0, dv1=th1-xp1, dv2=th2-xp2;
        float dvn = dv0*nx + dv1*ny + dv2*nz;
        float dt0 = ftanh(dv0-dvn*nx), dt1 = ftanh(dv1-dvn*ny), dt2 = ftanh(dv2-dvn*nz);
        float lon = dt0*fw0+dt1*fw1+dt2*fw2;
        float lat = dt0*lt0+dt1*lt1+dt2*lt2;
        float hNm = 0.5f*Nm;
        float ff0 = hNm*(lon*fw0 + lat*lt0);
        float ff1 = hNm*(lon*fw1 + lat*lt1);
        float ff2 = hNm*(lon*fw2 + lat*lt2);
        float a0=fs0+ff0, a1=fs1+ff1, a2=fs2+ff2;
        as0+=a0; as1+=a1; as2+=a2;
        ts0 += cc1*a2 - cc2*a1;
        ts1 += cc2*a0 - cc0*a2;
        ts2 += cc0*a1 - cc1*a0;
        size_t o3 = ((size_t)b*Nv + n)*3;
        out[O_FS+o3+0]=fs0; out[O_FS+o3+1]=fs1; out[O_FS+o3+2]=fs2;
        out[O_FF+o3+0]=ff0; out[O_FF+o3+1]=ff1; out[O_FF+o3+2]=ff2;
        out[O_IC+(size_t)b*Nv+n]=ic;
        out[O_THR+o3+0]=th0; out[O_THR+o3+1]=th1; out[O_THR+o3+2]=th2;
    }
    // reduce act-sum and torque
    #pragma unroll
    for (int o=16;o>0;o>>=1){
        as0 += __shfl_xor_sync(0xffffffffu, as0, o);
        as1 += __shfl_xor_sync(0xffffffffu, as1, o);
        as2 += __shfl_xor_sync(0xffffffffu, as2, o);
        ts0 += __shfl_xor_sync(0xffffffffu, ts0, o);
        ts1 += __shfl_xor_sync(0xffffffffu, ts1, o);
        ts2 += __shfl_xor_sync(0xffffffffu, ts2, o);
    }
    __syncthreads();   // sRed reuse guard
    if ((tid & 31) == 0) {
        int w = tid>>5;
        sRed[w][0]=as0; sRed[w][1]=as1; sRed[w][2]=as2;
        sRed[w][3]=ts0; sRed[w][4]=ts1; sRed[w][5]=ts2;
    }
    __syncthreads();

    // ---- finalize (tid 0) ----
    if (tid == 0) {
        float A0=0,A1=0,A2=0,T0=0,T1=0,T2=0;
        #pragma unroll
        for (int w=0;w<16;w++){
            A0+=sRed[w][0]; A1+=sRed[w][1]; A2+=sRed[w][2];
            T0+=sRed[w][3]; T1+=sRed[w][4]; T2+=sRed[w][5];
        }
        float tq0 = fminf(fmaxf(T0,-TQL),TQL);
        float tq1 = fminf(fmaxf(T1,-TQL),TQL);
        float tq2 = fminf(fmaxf(T2,-TQL),TQL);
        float a00=sIn[0],a01=sIn[1],a02=sIn[2];
        float a10=sIn[3],a11=sIn[4],a12=sIn[5];
        float a20=sIn[6],a21=sIn[7],a22=sIn[8];
        float c00=a11*a22-a12*a21, c01=a02*a21-a01*a22, c02=a01*a12-a02*a11;
        float c10=a12*a20-a10*a22, c11=a00*a22-a02*a20, c12=a02*a10-a00*a12;
        float c20=a10*a21-a11*a20, c21=a01*a20-a00*a21, c22=a00*a11-a01*a10;
        float det = a00*c00 + a01*c10 + a02*c20;
        float idet = 1.0f/det;
        float od0 = (c00*tq0 + c01*tq1 + c02*tq2)*idet;
        float od1 = (c10*tq0 + c11*tq1 + c12*tq2)*idet;
        float od2 = (c20*tq0 + c21*tq1 + c22*tq2)*idet;
        float tm = sTM, itm = 1.0f/tm;
        float xdd0 = A0*itm, xdd1 = A1*itm, xdd2 = (A2 - tm*GRAV)*itm;
        float nxd0 = xd0 + xdd0*DTv, nxd1 = xd1 + xdd1*DTv, nxd2 = xd2 + xdd2*DTv;
        float nx0 = xb0 + nxd0*DTv, nx1 = xb1 + nxd1*DTv, nx2 = xb2 + nxd2*DTv;
        float no0 = om0 + od0*DTv, no1 = om1 + od1*DTv, no2 = om2 + od2*DTv;
        float qw=q[b*4+0], qx=q[b*4+1], qy=q[b*4+2], qz=q[b*4+3];
        float hdt = 0.5f*DTv;
        float dqw = hdt*(-qx*no0 - qy*no1 - qz*no2);
        float dqx = hdt*( qw*no0 + qy*no2 - qz*no1);
        float dqy = hdt*( qw*no1 - qx*no2 + qz*no0);
        float dqz = hdt*( qw*no2 + qx*no1 - qy*no0);
        float nq0=qw+dqw, nq1=qx+dqx, nq2=qy+dqy, nq3=qz+dqz;
        float qni = 1.0f/(sqrtf(nq0*nq0+nq1*nq1+nq2*nq2+nq3*nq3)+1e-8f);
        nq0*=qni; nq1*=qni; nq2*=qni; nq3*=qni;

        out[O_NX +b*3+0]=nx0;  out[O_NX +b*3+1]=nx1;  out[O_NX +b*3+2]=nx2;
        out[O_NXD+b*3+0]=nxd0; out[O_NXD+b*3+1]=nxd1; out[O_NXD+b*3+2]=nxd2;
        out[O_NQ +b*4+0]=nq0;  out[O_NQ +b*4+1]=nq1;  out[O_NQ +b*4+2]=nq2; out[O_NQ+b*4+3]=nq3;
        out[O_NOM+b*3+0]=no0;  out[O_NOM+b*3+1]=no1;  out[O_NOM+b*3+2]=no2;
        out[O_XDD+b*3+0]=xdd0; out[O_XDD+b*3+1]=xdd1; out[O_XDD+b*3+2]=xdd2;
        out[O_OMD+b*3+0]=od0;  out[O_OMD+b*3+1]=od1;  out[O_OMD+b*3+2]=od2;
        out[O_TQ +b*3+0]=tq0;  out[O_TQ +b*3+1]=tq1;  out[O_TQ +b*3+2]=tq2;
        #pragma unroll
        for (int j=0;j<Dv;j++){
            float td = fminf(fmaxf(controls[b*2*Dv + Dv + j], -MAXPV), MAXPV);
            out[O_THD+(size_t)b*Dv+j] = td;
            float nth = thetas[b*Dv+j] + td*DTv;
            out[O_NTH+(size_t)b*Dv+j] = fminf(fmaxf(nth, -1.0f), 1.0f);
        }
    }
}

extern "C" void kernel_launch(void* const* d_in, const int* in_sizes, int n_in,
                              void* d_out, int out_size) {
    (void)in_sizes; (void)n_in; (void)out_size;
    phys_kernel<<<Bv, NTHR>>>(
        (const float*)d_in[0],  (const float*)d_in[1],  (const float*)d_in[2],
        (const float*)d_in[3],  (const float*)d_in[4],  (const float*)d_in[5],
        (const float*)d_in[6],  (const float*)d_in[7],  (const float*)d_in[8],
        (const float*)d_in[9],  (const float*)d_in[10], (const float*)d_in[11],
        (const float*)d_in[12], (const float*)d_in[13], (const float*)d_in[14],
        (const float*)d_in[15], (float*)d_out);
}

// round 9
// speedup vs baseline: 1.1221x; 1.1221x over previous
#include <cuda_runtime.h>
#include <math.h>

#define Bv 1024
#define Dv 8
#define Pv 128
#define Nv 1024
#define Hv 256
#define Wv 256

#define GRAV   9.8f
#define DTv    0.01f
#define TQL    200.0f
#define SIGMAv 0.03f
#define KST    5000.0f
#define BMASS  40.0f
#define MAXC   6.4f
#define MAXPV  0.5f
#define SQRT3v 1.7320508075688772f

// ---- output segment offsets (floats), tuple order of reference ----
#define O_NX   ((size_t)0)
#define O_NXD  (O_NX  + (size_t)Bv*3)
#define O_NQ   (O_NXD + (size_t)Bv*3)
#define O_NOM  (O_NQ  + (size_t)Bv*4)
#define O_NTH  (O_NOM + (size_t)Bv*3)
#define O_XDD  (O_NTH + (size_t)Bv*Dv)
#define O_OMD  (O_XDD + (size_t)Bv*3)
#define O_THD  (O_OMD + (size_t)Bv*3)
#define O_FS   (O_THD + (size_t)Bv*Dv)
#define O_FF   (O_FS  + (size_t)Bv*Nv*3)
#define O_IC   (O_FF  + (size_t)Bv*Nv*3)
#define O_TQ   (O_IC  + (size_t)Bv*Nv)
#define O_RP   (O_TQ  + (size_t)Bv*3)
#define O_THR  (O_RP  + (size_t)Bv*Nv*3)

// fast tanh via MUFU EX2 path; exact limits at +-inf arguments
__device__ __forceinline__ float ftanh(float v) {
    float e = __expf(2.0f * v);
    return 1.0f - __fdividef(2.0f, e + 1.0f);
}

__global__ __launch_bounds__(256, 4) void phys_kernel(
    const float* __restrict__ x,      const float* __restrict__ xd,
    const float* __restrict__ q,      const float* __restrict__ omega,
    const float* __restrict__ thetas, const float* __restrict__ controls,
    const float* __restrict__ z_grid, const float* __restrict__ z_grid_grad,
    const float* __restrict__ jp,     const float* __restrict__ jlp,
    const float* __restrict__ jlc,    const float* __restrict__ dpi,
    const float* __restrict__ dpm,    const float* __restrict__ bcog,
    const float* __restrict__ binert, const float* __restrict__ dd,
    float* __restrict__ out)
{
    const int b   = blockIdx.x;
    const int tid = threadIdx.x;

    __shared__ float sRw[9];
    __shared__ float sM[Dv][9];
    __shared__ float sT[Dv][3];
    __shared__ float sThr[Dv][3];
    __shared__ float sCL[Dv][3];
    __shared__ float sRI[Dv][9];
    __shared__ float sGdd[3];
    __shared__ float sGcog[3];
    __shared__ float sIn[9];
    __shared__ float sTM, sInvNC, sKD;
    __shared__ float sRed[8][6];
    // per-point state carried across the num_contacts barrier (7 floats/pt)
    __shared__ float sR0[Nv], sR1[Nv], sR2[Nv];
    __shared__ float sGX[Nv], sGY[Nv];
    __shared__ float sDH[Nv], sIC[Nv];

    const float xb0 = x[b*3+0], xb1 = x[b*3+1], xb2 = x[b*3+2];

    // ---- step A: R_world, gdd, total mass (tid 0) ----
    if (tid == 0) {
        float qw=q[b*4+0], qx=q[b*4+1], qy=q[b*4+2], qz=q[b*4+3];
        sRw[0]=1.f-2.f*(qy*qy+qz*qz); sRw[1]=2.f*(qx*qy-qw*qz); sRw[2]=2.f*(qx*qz+qw*qy);
        sRw[3]=2.f*(qx*qy+qw*qz); sRw[4]=1.f-2.f*(qx*qx+qz*qz); sRw[5]=2.f*(qy*qz-qw*qx);
        sRw[6]=2.f*(qx*qz-qw*qy); sRw[7]=2.f*(qy*qz+qw*qx); sRw[8]=1.f-2.f*(qx*qx+qy*qy);
        float tm = BMASS;
        #pragma unroll
        for (int d=0; d<Dv; d++) tm += dpm[d];
        sTM = tm;
        float d0=dd[0], d1=dd[1], d2=dd[2];
        sGdd[0]=sRw[0]*d0+sRw[1]*d1+sRw[2]*d2;
        sGdd[1]=sRw[3]*d0+sRw[4]*d1+sRw[5]*d2;
        sGdd[2]=sRw[6]*d0+sRw[7]*d1+sRw[8]*d2;
    }
    __syncthreads();

    // ---- step B: per-joint matrices (tids 0..7) ----
    if (tid < Dv) {
        const int d = tid;
        float th = thetas[b*Dv+d];
        float c = cosf(th), s = sinf(th);
        #pragma unroll
        for (int i=0;i<3;i++){
            sM[d][i*3+0] = c*sRw[i*3+0] - s*sRw[i*3+2];
            sM[d][i*3+1] = sRw[i*3+1];
            sM[d][i*3+2] = s*sRw[i*3+0] + c*sRw[i*3+2];
        }
        float jp0=jp[d*3+0], jp1=jp[d*3+1], jp2=jp[d*3+2];
        sT[d][0]=sRw[0]*jp0+sRw[1]*jp1+sRw[2]*jp2 + xb0;
        sT[d][1]=sRw[3]*jp0+sRw[4]*jp1+sRw[5]*jp2 + xb1;
        sT[d][2]=sRw[6]*jp0+sRw[7]*jp1+sRw[8]*jp2 + xb2;
        float l0=jlc[d*3+0], l1=jlc[d*3+1], l2=jlc[d*3+2];
        sCL[d][0] = c*l0 + s*l2 + jp0;
        sCL[d][1] = l1 + jp1;
        sCL[d][2] = -s*l0 + c*l2 + jp2;
        const float* Im = dpi + d*9;
        float t0[3], t1[3], t2[3];
        #pragma unroll
        for (int j=0;j<3;j++){
            t0[j] =  c*Im[0*3+j] + s*Im[2*3+j];
            t1[j] =  Im[1*3+j];
            t2[j] = -s*Im[0*3+j] + c*Im[2*3+j];
        }
        sRI[d][0]= c*t0[0]+s*t0[2]; sRI[d][1]=t0[1]; sRI[d][2]=-s*t0[0]+c*t0[2];
        sRI[d][3]= c*t1[0]+s*t1[2]; sRI[d][4]=t1[1]; sRI[d][5]=-s*t1[0]+c*t1[2];
        sRI[d][6]= c*t2[0]+s*t2[2]; sRI[d][7]=t2[1]; sRI[d][8]=-s*t2[0]+c*t2[2];
        float d0=dd[0], d1=dd[1], d2=dd[2];
        float u0 = c*d0 + s*d2, u1 = d1, u2 = -s*d0 + c*d2;
        float vc = controls[b*2*Dv + d];
        sThr[d][0]=(sRw[0]*u0+sRw[1]*u1+sRw[2]*u2)*vc;
        sThr[d][1]=(sRw[3]*u0+sRw[4]*u1+sRw[5]*u2)*vc;
        sThr[d][2]=(sRw[6]*u0+sRw[7]*u1+sRw[8]*u2)*vc;
    }
    __syncthreads();

    // ---- step C: cog + world inertia (tid 0) ----
    if (tid == 0) {
        float tm = sTM;
        float cg0 = BMASS*bcog[0], cg1 = BMASS*bcog[1], cg2 = BMASS*bcog[2];
        #pragma unroll
        for (int d=0; d<Dv; d++){
            float m = dpm[d];
            cg0 += m*sCL[d][0]; cg1 += m*sCL[d][1]; cg2 += m*sCL[d][2];
        }
        float itm = 1.0f/tm;
        cg0*=itm; cg1*=itm; cg2*=itm;
        float Io[9];
        #pragma unroll
        for (int i=0;i<9;i++) Io[i] = binert[i];
        {
            float e0=bcog[0]-cg0, e1=bcog[1]-cg1, e2=bcog[2]-cg2;
            float s2 = e0*e0+e1*e1+e2*e2;
            Io[0]+=BMASS*(s2-e0*e0); Io[1]+=BMASS*(-e0*e1);  Io[2]+=BMASS*(-e0*e2);
            Io[3]+=BMASS*(-e1*e0);  Io[4]+=BMASS*(s2-e1*e1); Io[5]+=BMASS*(-e1*e2);
            Io[6]+=BMASS*(-e2*e0);  Io[7]+=BMASS*(-e2*e1);   Io[8]+=BMASS*(s2-e2*e2);
        }
        #pragma unroll
        for (int d=0; d<Dv; d++){
            float m = dpm[d];
            float e0=sCL[d][0]-cg0, e1=sCL[d][1]-cg1, e2=sCL[d][2]-cg2;
            float s2 = e0*e0+e1*e1+e2*e2;
            Io[0]+=sRI[d][0]+m*(s2-e0*e0); Io[1]+=sRI[d][1]+m*(-e0*e1);  Io[2]+=sRI[d][2]+m*(-e0*e2);
            Io[3]+=sRI[d][3]+m*(-e1*e0);  Io[4]+=sRI[d][4]+m*(s2-e1*e1); Io[5]+=sRI[d][5]+m*(-e1*e2);
            Io[6]+=sRI[d][6]+m*(-e2*e0);  Io[7]+=sRI[d][7]+m*(-e2*e1);   Io[8]+=sRI[d][8]+m*(s2-e2*e2);
        }
        float tmp[9];
        #pragma unroll
        for (int i=0;i<3;i++)
            #pragma unroll
            for (int j=0;j<3;j++)
                tmp[i*3+j] = sRw[i*3+0]*Io[0*3+j] + sRw[i*3+1]*Io[1*3+j] + sRw[i*3+2]*Io[2*3+j];
        #pragma unroll
        for (int i=0;i<3;i++)
            #pragma unroll
            for (int j=0;j<3;j++)
                sIn[i*3+j] = tmp[i*3+0]*sRw[j*3+0] + tmp[i*3+1]*sRw[j*3+1] + tmp[i*3+2]*sRw[j*3+2];
        sGcog[0]=sRw[0]*cg0+sRw[1]*cg1+sRw[2]*cg2 + xb0;
        sGcog[1]=sRw[3]*cg0+sRw[4]*cg1+sRw[5]*cg2 + xb1;
        sGcog[2]=sRw[6]*cg0+sRw[7]*cg1+sRw[8]*cg2 + xb2;
    }
    __syncthreads();

    // ---- phase A: points, gathers, contact ----
    const float* zg  = z_grid      + (size_t)b*Hv*Wv;
    const float* gxg = z_grid_grad + (size_t)b*2*Hv*Wv;
    const float* gyg = gxg + (size_t)Hv*Wv;
    float* __restrict__ outRP = out + O_RP + (size_t)b*Nv*3;

    float icsum = 0.f;
    #pragma unroll
    for (int k=0;k<4;k++){
        int n = tid + k*256;
        int d = n >> 7;
        const float* lp = jlp + (size_t)n*3;
        float l0=__ldg(lp+0), l1=__ldg(lp+1), l2=__ldg(lp+2);
        float r0 = sM[d][0]*l0 + sM[d][1]*l1 + sM[d][2]*l2 + sT[d][0];
        float r1 = sM[d][3]*l0 + sM[d][4]*l1 + sM[d][5]*l2 + sT[d][1];
        float r2 = sM[d][6]*l0 + sM[d][7]*l1 + sM[d][8]*l2 + sT[d][2];
        sR0[n]=r0; sR1[n]=r1; sR2[n]=r2;
        unsigned o3 = (unsigned)n*3u;
        outRP[o3+0]=r0; outRP[o3+1]=r1; outRP[o3+2]=r2;

        float u = (r0 + MAXC) / (2.0f*MAXC) * (float)(Wv-1);
        float v = (r1 + MAXC) / (2.0f*MAXC) * (float)(Hv-1);
        u = fminf(fmaxf(u, 0.0f), (float)(Wv-1) - 1e-5f);
        v = fminf(fmaxf(v, 0.0f), (float)(Hv-1) - 1e-5f);
        int u0 = (int)u, v0 = (int)v;
        float fu = u - (float)u0, fv = v - (float)v0;
        int idx = v0*Wv + u0;
        float w00=(1.f-fu)*(1.f-fv), w01=fu*(1.f-fv), w10=(1.f-fu)*fv, w11=fu*fv;
        float zs = __ldg(zg+idx)*w00 + __ldg(zg+idx+1)*w01 + __ldg(zg+idx+Wv)*w10 + __ldg(zg+idx+Wv+1)*w11;
        float gx = __ldg(gxg+idx)*w00 + __ldg(gxg+idx+1)*w01 + __ldg(gxg+idx+Wv)*w10 + __ldg(gxg+idx+Wv+1)*w11;
        float gy = __ldg(gyg+idx)*w00 + __ldg(gyg+idx+1)*w01 + __ldg(gyg+idx+Wv)*w10 + __ldg(gyg+idx+Wv+1)*w11;

        float nz = rsqrtf(gx*gx + gy*gy + 1.0f);  // n=[-gx,-gy,1]*nz
        float dh = (r2 - zs)*nz;
        float ic = 0.5f*(1.0f + ftanh(-dh*(SQRT3v/SIGMAv)));
        sGX[n]=gx; sGY[n]=gy;
        sDH[n]=dh; sIC[n]=ic; icsum += ic;
    }
    // reduce num_contacts
    #pragma unroll
    for (int o=16;o>0;o>>=1) icsum += __shfl_xor_sync(0xffffffffu, icsum, o);
    if ((tid & 31) == 0) sRed[tid>>5][0] = icsum;
    __syncthreads();
    if (tid == 0) {
        float s = 0.f;
        #pragma unroll
        for (int w=0;w<8;w++) s += sRed[w][0];
        float nc = fmaxf(s, 1.0f);
        sInvNC = 1.0f/nc;
        sKD = sqrtf(sTM*KST/nc);
    }
    __syncthreads();

    // ---- phase B: forces ----
    const float xd0=xd[b*3+0], xd1=xd[b*3+1], xd2=xd[b*3+2];
    const float om0=omega[b*3+0], om1=omega[b*3+1], om2=omega[b*3+2];
    const float invnc = sInvNC, kd = sKD;
    const float g0=sGdd[0], g1=sGdd[1], g2=sGdd[2];
    const float gc0=sGcog[0], gc1=sGcog[1], gc2=sGcog[2];
    float* __restrict__ outFS  = out + O_FS  + (size_t)b*Nv*3;
    float* __restrict__ outFF  = out + O_FF  + (size_t)b*Nv*3;
    float* __restrict__ outIC  = out + O_IC  + (size_t)b*Nv;
    float* __restrict__ outTHR = out + O_THR + (size_t)b*Nv*3;

    float as0=0.f, as1=0.f, as2=0.f, ts0=0.f, ts1=0.f, ts2=0.f;
    #pragma unroll
    for (int k=0;k<4;k++){
        int n = tid + k*256;
        int d = n >> 7;
        float cc0 = sR0[n]-gc0, cc1 = sR1[n]-gc1, cc2 = sR2[n]-gc2;
        float xp0 = xd0 + om1*cc2 - om2*cc1;
        float xp1 = xd1 + om2*cc0 - om0*cc2;
        float xp2 = xd2 + om0*cc1 - om1*cc0;
        float gx=sGX[n], gy=sGY[n];
        float inv = rsqrtf(gx*gx + gy*gy + 1.0f);
        float nx=-gx*inv, ny=-gy*inv, nz=inv;
        float ic=sIC[n], dh=sDH[n];
        float xdn = xp0*nx + xp1*ny + xp2*nz;
        float sf = -(KST*dh*ic + kd*xdn)*ic*invnc;
        float fs0 = sf*nx, fs1 = sf*ny, fs2 = sf*nz;
        float Nm = fabsf(sf);                     // |F_spring|: n is unit
        float gn = g0*nx + g1*ny + g2*nz;
        float fw0 = g0-gn*nx, fw1 = g1-gn*ny, fw2 = g2-gn*nz;
        float fni = rsqrtf(fw0*fw0+fw1*fw1+fw2*fw2);
        fw0*=fni; fw1*=fni; fw2*=fni;
        // lat = cross(fwd, n): orthonormal inputs -> already unit
        float lt0 = fw1*nz - fw2*ny, lt1 = fw2*nx - fw0*nz, lt2 = fw0*ny - fw1*nx;
        float th0=sThr[d][0], th1=sThr[d][1], th2=sThr[d][2];
        float dv0=th0-xp0, dv1=th1-xp1, dv2=th2-xp2;
        float dvn = dv0*nx + dv1*ny + dv2*nz;
        float dt0 = ftanh(dv0-dvn*nx), dt1 = ftanh(dv1-dvn*ny), dt2 = ftanh(dv2-dvn*nz);
        float lon = dt0*fw0+dt1*fw1+dt2*fw2;
        float lat = dt0*lt0+dt1*lt1+dt2*lt2;
        float hNm = 0.5f*Nm;
        float ff0 = hNm*(lon*fw0 + lat*lt0);
        float ff1 = hNm*(lon*fw1 + lat*lt1);
        float ff2 = hNm*(lon*fw2 + lat*lt2);
        float a0=fs0+ff0, a1=fs1+ff1, a2=fs2+ff2;
        as0+=a0; as1+=a1; as2+=a2;
        ts0 += cc1*a2 - cc2*a1;
        ts1 += cc2*a0 - cc0*a2;
        ts2 += cc0*a1 - cc1*a0;
        unsigned o3 = (unsigned)n*3u;
        outFS[o3+0]=fs0; outFS[o3+1]=fs1; outFS[o3+2]=fs2;
        outFF[o3+0]=ff0; outFF[o3+1]=ff1; outFF[o3+2]=ff2;
        outIC[n]=ic;
        outTHR[o3+0]=th0; outTHR[o3+1]=th1; outTHR[o3+2]=th2;
    }
    // reduce act-sum and torque
    #pragma unroll
    for (int o=16;o>0;o>>=1){
        as0 += __shfl_xor_sync(0xffffffffu, as0, o);
        as1 += __shfl_xor_sync(0xffffffffu, as1, o);
        as2 += __shfl_xor_sync(0xffffffffu, as2, o);
        ts0 += __shfl_xor_sync(0xffffffffu, ts0, o);
        ts1 += __shfl_xor_sync(0xffffffffu, ts1, o);
        ts2 += __shfl_xor_sync(0xffffffffu, ts2, o);
    }
    __syncthreads();   // sRed reuse guard
    if ((tid & 31) == 0) {
        int w = tid>>5;
        sRed[w][0]=as0; sRed[w][1]=as1; sRed[w][2]=as2;
        sRed[w][3]=ts0; sRed[w][4]=ts1; sRed[w][5]=ts2;
    }
    __syncthreads();

    // ---- finalize (tid 0) ----
    if (tid == 0) {
        float A0=0,A1=0,A2=0,T0=0,T1=0,T2=0;
        #pragma unroll
        for (int w=0;w<8;w++){
            A0+=sRed[w][0]; A1+=sRed[w][1]; A2+=sRed[w][2];
            T0+=sRed[w][3]; T1+=sRed[w][4]; T2+=sRed[w][5];
        }
        float tq0 = fminf(fmaxf(T0,-TQL),TQL);
        float tq1 = fminf(fmaxf(T1,-TQL),TQL);
        float tq2 = fminf(fmaxf(T2,-TQL),TQL);
        float a00=sIn[0],a01=sIn[1],a02=sIn[2];
        float a10=sIn[3],a11=sIn[4],a12=sIn[5];
        float a20=sIn[6],a21=sIn[7],a22=sIn[8];
        float c00=a11*a22-a12*a21, c01=a02*a21-a01*a22, c02=a01*a12-a02*a11;
        float c10=a12*a20-a10*a22, c11=a00*a22-a02*a20, c12=a02*a10-a00*a12;
        float c20=a10*a21-a11*a20, c21=a01*a20-a00*a21, c22=a00*a11-a01*a10;
        float det = a00*c00 + a01*c10 + a02*c20;
        float idet = 1.0f/det;
        float od0 = (c00*tq0 + c01*tq1 + c02*tq2)*idet;
        float od1 = (c10*tq0 + c11*tq1 + c12*tq2)*idet;
        float od2 = (c20*tq0 + c21*tq1 + c22*tq2)*idet;
        float tm = sTM, itm = 1.0f/tm;
        float xdd0 = A0*itm, xdd1 = A1*itm, xdd2 = (A2 - tm*GRAV)*itm;
        float nxd0 = xd0 + xdd0*DTv, nxd1 = xd1 + xdd1*DTv, nxd2 = xd2 + xdd2*DTv;
        float nx0 = xb0 + nxd0*DTv, nx1 = xb1 + nxd1*DTv, nx2 = xb2 + nxd2*DTv;
        float no0 = om0 + od0*DTv, no1 = om1 + od1*DTv, no2 = om2 + od2*DTv;
        float qw=q[b*4+0], qx=q[b*4+1], qy=q[b*4+2], qz=q[b*4+3];
        float hdt = 0.5f*DTv;
        float dqw = hdt*(-qx*no0 - qy*no1 - qz*no2);
        float dqx = hdt*( qw*no0 + qy*no2 - qz*no1);
        float dqy = hdt*( qw*no1 - qx*no2 + qz*no0);
        float dqz = hdt*( qw*no2 + qx*no1 - qy*no0);
        float nq0=qw+dqw, nq1=qx+dqx, nq2=qy+dqy, nq3=qz+dqz;
        float qni = 1.0f/(sqrtf(nq0*nq0+nq1*nq1+nq2*nq2+nq3*nq3)+1e-8f);
        nq0*=qni; nq1*=qni; nq2*=qni; nq3*=qni;

        out[O_NX +b*3+0]=nx0;  out[O_NX +b*3+1]=nx1;  out[O_NX +b*3+2]=nx2;
        out[O_NXD+b*3+0]=nxd0; out[O_NXD+b*3+1]=nxd1; out[O_NXD+b*3+2]=nxd2;
        out[O_NQ +b*4+0]=nq0;  out[O_NQ +b*4+1]=nq1;  out[O_NQ +b*4+2]=nq2; out[O_NQ+b*4+3]=nq3;
        out[O_NOM+b*3+0]=no0;  out[O_NOM+b*3+1]=no1;  out[O_NOM+b*3+2]=no2;
        out[O_XDD+b*3+0]=xdd0; out[O_XDD+b*3+1]=xdd1; out[O_XDD+b*3+2]=xdd2;
        out[O_OMD+b*3+0]=od0;  out[O_OMD+b*3+1]=od1;  out[O_OMD+b*3+2]=od2;
        out[O_TQ +b*3+0]=tq0;  out[O_TQ +b*3+1]=tq1;  out[O_TQ +b*3+2]=tq2;
        #pragma unroll
        for (int j=0;j<Dv;j++){
            float td = fminf(fmaxf(controls[b*2*Dv + Dv + j], -MAXPV), MAXPV);
            out[O_THD+(size_t)b*Dv+j] = td;
            float nth = thetas[b*Dv+j] + td*DTv;
            out[O_NTH+(size_t)b*Dv+j] = fminf(fmaxf(nth, -1.0f), 1.0f);
        }
    }
}

extern "C" void kernel_launch(void* const* d_in, const int* in_sizes, int n_in,
                              void* d_out, int out_size) {
    (void)in_sizes; (void)n_in; (void)out_size;
    phys_kernel<<<Bv, 256>>>(
        (const float*)d_in[0],  (const float*)d_in[1],  (const float*)d_in[2],
        (const float*)d_in[3],  (const float*)d_in[4],  (const float*)d_in[5],
        (const float*)d_in[6],  (const float*)d_in[7],  (const float*)d_in[8],
        (const float*)d_in[9],  (const float*)d_in[10], (const float*)d_in[11],
        (const float*)d_in[12], (const float*)d_in[13], (const float*)d_in[14],
        (const float*)d_in[15], (float*)d_out);
}